// round 14
// baseline (speedup 1.0000x reference)
#include <cuda_runtime.h>
#include <cuda_bf16.h>
#include <stdint.h>
#include <math.h>

#define GAMMA 0.25f
#define RSTRIDE 528              // smem row pitch bytes (256 bf16 + 16B pad)
#define ATILE  67584             // 128 * RSTRIDE
#define QSTR   528

// ---------------------------------------------------------------------------
// device scratch (static — no cudaMalloc allowed)
// ---------------------------------------------------------------------------
__device__ __align__(16) __nv_bfloat16 g_Bg[14 * 128 * 256];    // 14 B tiles [n][k]
__device__ __align__(16) __nv_bfloat16 g_qbf[65536 * 256];      // Q scratch bf16
__device__ __align__(16) __nv_bfloat16 g_kbf[65536 * 256];      // K scratch bf16

__device__ __forceinline__ uint32_t smem_u32(const void* p) {
    uint32_t a;
    asm("{ .reg .u64 t; cvta.to.shared.u64 t, %1; cvt.u32.u64 %0, t; }" : "=r"(a) : "l"(p));
    return a;
}

#define LDMX4(r0, r1, r2, r3, addr) \
    asm volatile("ldmatrix.sync.aligned.m8n8.x4.shared.b16 {%0,%1,%2,%3}, [%4];" \
                 : "=r"(r0), "=r"(r1), "=r"(r2), "=r"(r3) : "r"(addr))

#define MMA16816(d, a, b) \
    asm volatile("mma.sync.aligned.m16n8k16.row.col.f32.bf16.bf16.f32 " \
                 "{%0,%1,%2,%3}, {%4,%5,%6,%7}, {%8,%9}, {%0,%1,%2,%3};" \
                 : "+f"((d)[0]), "+f"((d)[1]), "+f"((d)[2]), "+f"((d)[3]) \
                 : "r"((a)[0]), "r"((a)[1]), "r"((a)[2]), "r"((a)[3]), \
                   "r"((b)[0]), "r"((b)[1]))

#define CPA16(dst, src) \
    asm volatile("cp.async.cg.shared.global [%0], [%1], 16;" :: "r"(dst), "l"(src) : "memory")
#define CPA_COMMIT() asm volatile("cp.async.commit_group;" ::: "memory")

// ---------------------------------------------------------------------------
__device__ __forceinline__ float block_reduce_256(float v, float* red) {
#pragma unroll
    for (int o = 16; o > 0; o >>= 1) v += __shfl_xor_sync(0xffffffffu, v, o);
    int w = threadIdx.x >> 5;
    if ((threadIdx.x & 31) == 0) red[w] = v;
    __syncthreads();
    if (threadIdx.x < 8) {
        v = red[threadIdx.x];
#pragma unroll
        for (int o = 4; o > 0; o >>= 1) v += __shfl_xor_sync(0x000000ffu, v, o);
    }
    return v;
}

// ---------------------------------------------------------------------------
// kprepB: build 14 dense bf16 B tiles [n][k] — one uint4 store per thread
// ---------------------------------------------------------------------------
extern "C" __global__ void __launch_bounds__(256)
kprepB(const float* __restrict__ Wm, const float* __restrict__ WQ,
       const float* __restrict__ WK, const float* __restrict__ We) {
    int nt = blockIdx.x;
    __nv_bfloat16* img = g_Bg + (size_t)nt * 128 * 256;
    int f0 = (blockIdx.y * 256 + threadIdx.x) * 8;   // grid.y = 16
    int n = f0 >> 8, k0 = f0 & 255;
    __nv_bfloat16 tmp[8];
#pragma unroll
    for (int i = 0; i < 8; i++) {
        int k = k0 + i;
        float v;
        if (nt < 8)        v = Wm[k * 1024 + nt * 128 + n];
        else if (nt < 10)  v = WQ[((nt - 8) * 128 + n) * 256 + k];
        else if (nt < 12)  v = WK[((nt - 10) * 128 + n) * 256 + k];
        else {
            int ng = (nt - 12) * 128 + n;
            v = (ng < 192) ? We[k * 192 + ng] : 0.f;
        }
        tmp[i] = __float2bfloat16(v);
    }
    *(uint4*)(img + f0) = *(uint4*)tmp;
}

// ---------------------------------------------------------------------------
// kgemm: grid 512, 256 threads (8 warps, warp tile 32x64).
//   A resident; 14 N-tiles, cp.async dbuf B. Mainloop software-pipelined:
//   ldmatrix fragments double-buffered so MMAs of step ks overlap the LDSM
//   latency of step ks+1.
//   Fused: z->bf16 + quad_z/bias/pos, phi_mem relu^2, Q/K bf16 stores,
//   x-side consume on nt=12/13.
// ---------------------------------------------------------------------------
extern "C" __global__ void __launch_bounds__(256, 1)
kgemm(const float* __restrict__ x, const float* __restrict__ z,
      const float* __restrict__ eb, const float* __restrict__ pos,
      const float* __restrict__ vb, float* __restrict__ out) {
    extern __shared__ char smem[];
    __shared__ float red[8], red2[8], mred[8];
    uint32_t sb = smem_u32(smem);
    const uint32_t As = sb;
    int tid = threadIdx.x, lane = tid & 31, w = tid >> 5;
    int wm = w >> 1, wn = w & 1;
    int mtile = blockIdx.x;

    // prefetch B tile 0 -> buf 0
    {
        const char* src = (const char*)(g_Bg);
#pragma unroll
        for (int i = 0; i < 16; i++) {
            int f = tid + i * 256;
            uint32_t dst = sb + ATILE + (f >> 5) * RSTRIDE + (f & 31) * 16;
            CPA16(dst, src + f * 16);
        }
        CPA_COMMIT();
    }

    // --- A load: z f32 -> bf16 smem + fused z statistics ---
    const float* zb = z + (size_t)mtile * 128 * 256;
    float zacc0 = 0.f, zacc1 = 0.f;
#pragma unroll
    for (int i = 0; i < 16; i++) {
        int f = tid + i * 256;               // chunk of 8 elems
        int row = f >> 5, c8 = (f & 31) * 8;
        const float4* zp = (const float4*)(zb + row * 256 + c8);
        float4 v0 = zp[0], v1 = zp[1];
        int prow = row & 63;
        float4 e0 = *(const float4*)(eb + c8);
        float4 e1 = *(const float4*)(eb + c8 + 4);
        float4 p0 = *(const float4*)(pos + prow * 256 + c8);
        float4 p1 = *(const float4*)(pos + prow * 256 + c8 + 4);
        float t =
            v0.x * (0.5f * v0.x - e0.x - p0.x) + v0.y * (0.5f * v0.y - e0.y - p0.y) +
            v0.z * (0.5f * v0.z - e0.z - p0.z) + v0.w * (0.5f * v0.w - e0.w - p0.w) +
            v1.x * (0.5f * v1.x - e1.x - p1.x) + v1.y * (0.5f * v1.y - e1.y - p1.y) +
            v1.z * (0.5f * v1.z - e1.z - p1.z) + v1.w * (0.5f * v1.w - e1.w - p1.w);
        if (i < 8) zacc0 += t; else zacc1 += t;
        uint4 pk;
        __nv_bfloat162 bt;
        bt = __floats2bfloat162_rn(v0.x, v0.y); pk.x = *(uint32_t*)&bt;
        bt = __floats2bfloat162_rn(v0.z, v0.w); pk.y = *(uint32_t*)&bt;
        bt = __floats2bfloat162_rn(v1.x, v1.y); pk.z = *(uint32_t*)&bt;
        bt = __floats2bfloat162_rn(v1.z, v1.w); pk.w = *(uint32_t*)&bt;
        *(uint4*)(smem + row * RSTRIDE + (f & 31) * 16) = pk;
    }

    // prefetch B tile 1 -> buf 1
    {
        const char* src = (const char*)(g_Bg + (size_t)128 * 256);
#pragma unroll
        for (int i = 0; i < 16; i++) {
            int f = tid + i * 256;
            uint32_t dst = sb + ATILE * 2 + (f >> 5) * RSTRIDE + (f & 31) * 16;
            CPA16(dst, src + f * 16);
        }
        CPA_COMMIT();
    }

    float msum = 0.f;          // phi_mem (subtract)
    float xsum = 0.f;          // quad_x - phi_vis - phi_enc (add)
    const float* xb = x + (size_t)mtile * 2 * 12288;
    int lrow = lane & 15, lhi = lane >> 4;

    // per-warp ldmatrix base addresses (advance 32B per ks)
    uint32_t aAddr0 = As + (wm * 32 + 0 * 16 + lrow) * RSTRIDE + lhi * 16;
    uint32_t aAddr1 = As + (wm * 32 + 1 * 16 + lrow) * RSTRIDE + lhi * 16;

    for (int nt = 0; nt < 14; nt++) {
        uint32_t Bs = sb + ATILE + (uint32_t)(nt & 1) * ATILE;
        if (nt == 13) asm volatile("cp.async.wait_group 0;" ::: "memory");
        else          asm volatile("cp.async.wait_group 1;" ::: "memory");
        __syncthreads();

        uint32_t bAddr[4];
#pragma unroll
        for (int bi = 0; bi < 4; bi++)
            bAddr[bi] = Bs + (wn * 64 + bi * 16 + lrow) * RSTRIDE + lhi * 16;

        float acc[2][8][4];
#pragma unroll
        for (int mi = 0; mi < 2; mi++)
#pragma unroll
            for (int nf = 0; nf < 8; nf++)
#pragma unroll
                for (int r = 0; r < 4; r++) acc[mi][nf][r] = 0.f;

        // --- software-pipelined mainloop: frags double-buffered ---
        uint32_t af[2][2][4], bf[2][4][4];
        // prologue: load ks=0 into buf 0
        LDMX4(af[0][0][0], af[0][0][1], af[0][0][2], af[0][0][3], aAddr0);
        LDMX4(af[0][1][0], af[0][1][1], af[0][1][2], af[0][1][3], aAddr1);
#pragma unroll
        for (int bi = 0; bi < 4; bi++)
            LDMX4(bf[0][bi][0], bf[0][bi][1], bf[0][bi][2], bf[0][bi][3], bAddr[bi]);

#pragma unroll
        for (int ks = 0; ks < 16; ks++) {
            int cur = ks & 1, nxt = cur ^ 1;
            if (ks < 15) {
                uint32_t coff = (ks + 1) * 32;
                LDMX4(af[nxt][0][0], af[nxt][0][1], af[nxt][0][2], af[nxt][0][3], aAddr0 + coff);
                LDMX4(af[nxt][1][0], af[nxt][1][1], af[nxt][1][2], af[nxt][1][3], aAddr1 + coff);
#pragma unroll
                for (int bi = 0; bi < 4; bi++)
                    LDMX4(bf[nxt][bi][0], bf[nxt][bi][1], bf[nxt][bi][2], bf[nxt][bi][3],
                          bAddr[bi] + coff);
            }
#pragma unroll
            for (int mi = 0; mi < 2; mi++)
#pragma unroll
                for (int bi = 0; bi < 4; bi++) {
                    uint32_t blo[2] = { bf[cur][bi][0], bf[cur][bi][2] };
                    uint32_t bhi[2] = { bf[cur][bi][1], bf[cur][bi][3] };
                    MMA16816(acc[mi][bi * 2 + 0], af[cur][mi], blo);
                    MMA16816(acc[mi][bi * 2 + 1], af[cur][mi], bhi);
                }
        }
        __syncthreads();   // all warps done reading buf (nt&1)

        // prefetch B[nt+2] into the buffer just freed
        if (nt + 2 < 14) {
            const char* src = (const char*)(g_Bg + (size_t)(nt + 2) * 128 * 256);
            uint32_t dstb = sb + ATILE + (uint32_t)(nt & 1) * ATILE;
#pragma unroll
            for (int i = 0; i < 16; i++) {
                int f = tid + i * 256;
                CPA16(dstb + (f >> 5) * RSTRIDE + (f & 31) * 16, src + f * 16);
            }
            CPA_COMMIT();
        }

        // ---- epilogue for this N-tile ----
        if (nt < 8) {
            // phi_mem: relu^2 reduce in-register
#pragma unroll
            for (int mi = 0; mi < 2; mi++)
#pragma unroll
                for (int nf = 0; nf < 8; nf++)
#pragma unroll
                    for (int r = 0; r < 4; r++) {
                        float v = fmaxf(acc[mi][nf][r], 0.f);
                        msum += v * v;
                    }
        } else if (nt < 12) {
            __nv_bfloat16* gout = (nt < 10) ? g_qbf : g_kbf;
            int tc = (nt < 10) ? (nt - 8) : (nt - 10);
            int colbase = tc * 128 + wn * 64 + (lane & 3) * 2;
            int rowbase = mtile * 128 + wm * 32 + (lane >> 2);
#pragma unroll
            for (int mi = 0; mi < 2; mi++)
#pragma unroll
                for (int nf = 0; nf < 8; nf++) {
                    int col = colbase + nf * 8;
                    int r0 = rowbase + mi * 16;
                    __nv_bfloat162 lo = __floats2bfloat162_rn(acc[mi][nf][0], acc[mi][nf][1]);
                    __nv_bfloat162 hi = __floats2bfloat162_rn(acc[mi][nf][2], acc[mi][nf][3]);
                    *(uint32_t*)(gout + (size_t)r0 * 256 + col) = *(uint32_t*)&lo;
                    *(uint32_t*)(gout + (size_t)(r0 + 8) * 256 + col) = *(uint32_t*)&hi;
                }
        } else {
            // enc tiles: consume accumulators directly against x (coalesced).
            // k = (nt-12)*128 + wn*64 + nf*8 + (lane&3)*2 + r  (valid k<192)
            int tc = nt - 12;
            if (!(tc == 1 && wn == 1)) {           // those cols are k>=192 (pad)
                int c = tc * 2 + wn;               // channel = k>>6
#pragma unroll
                for (int mi = 0; mi < 2; mi++)
#pragma unroll
                    for (int rp = 0; rp < 2; rp++) {
                        int l = wm * 32 + mi * 16 + rp * 8 + (lane >> 2);  // local row
                        int p = l & 63;
                        int jj = (p & 7) * 8 + (lane & 3) * 2;
                        size_t base0 = (size_t)(l >> 6) * 12288 + c * 4096 + (p >> 3) * 8 * 64 + jj;
#pragma unroll
                        for (int nf = 0; nf < 8; nf++) {
                            size_t off = base0 + nf * 64;  // ii = (p>>3)*8 + nf
                            float2 xv = *(const float2*)(xb + off);
                            float2 vv = *(const float2*)(vb + (off - (size_t)(l >> 6) * 12288));
                            float a0 = acc[mi][nf][rp * 2 + 0];
                            float a1 = acc[mi][nf][rp * 2 + 1];
                            xsum += xv.x * (0.5f * xv.x - vv.x - a0)
                                  + xv.y * (0.5f * xv.y - vv.y - a1);
                        }
                    }
            }
        }
    }

    // ---- final per-batch reductions: out[b] = zterms + xterms - phi_mem ----
    float wsum = xsum - msum;          // this thread's batch = wm>>1
#pragma unroll
    for (int o = 16; o > 0; o >>= 1) wsum += __shfl_xor_sync(0xffffffffu, wsum, o);
    if (lane == 0) mred[w] = wsum;
    float t0 = block_reduce_256(zacc0, red);
    float t1 = block_reduce_256(zacc1, red2);
    __syncthreads();
    if (tid == 0) {
        out[2 * mtile]     = t0 + (mred[0] + mred[1] + mred[2] + mred[3]);
        out[2 * mtile + 1] = t1 + (mred[4] + mred[5] + mred[6] + mred[7]);
    }
}

// ---------------------------------------------------------------------------
// kalite: out[b] -= phi_att. Logits via mma.sync from bf16 Q,K scratch.
//   Block = batch b; warp w = head w, two 32-row tasks sequentially
//   (halves acc registers -> 2 CTAs/SM). Overlaps kgemm tail waves.
// ---------------------------------------------------------------------------
extern "C" __global__ void __launch_bounds__(256, 2)
kalite(float* __restrict__ out) {
    extern __shared__ char sm[];
    __shared__ float red[8];
    uint32_t sb = smem_u32(sm);
    uint32_t Qs = sb, Ks = sb + 64 * QSTR;
    int b = blockIdx.x, tid = threadIdx.x, lane = tid & 31, w = tid >> 5;

    const uint4* qsrc = (const uint4*)(g_qbf + (size_t)b * 64 * 256);
    const uint4* ksrc = (const uint4*)(g_kbf + (size_t)b * 64 * 256);
#pragma unroll
    for (int i = 0; i < 8; i++) {
        int c = tid + i * 256;               // 2048 chunks each
        int row = c >> 5, cc = (c & 31) * 16;
        *(uint4*)(sm + row * QSTR + cc) = qsrc[c];
        *(uint4*)(sm + 64 * QSTR + row * QSTR + cc) = ksrc[c];
    }
    __syncthreads();

    int lrow = lane & 15, lhi = lane >> 4;
    float att = 0.f;

#pragma unroll
    for (int it = 0; it < 2; it++) {         // row-half of this head's 64 rows
        float acc[2][8][4];
#pragma unroll
        for (int mf = 0; mf < 2; mf++)
#pragma unroll
            for (int nf = 0; nf < 8; nf++)
#pragma unroll
                for (int r = 0; r < 4; r++) acc[mf][nf][r] = 0.f;

#pragma unroll
        for (int kc = 0; kc < 2; kc++) {
            uint32_t coff = w * 64 + kc * 32 + lhi * 16;
            uint32_t a[2][4], bb[4][4];
#pragma unroll
            for (int mf = 0; mf < 2; mf++)
                LDMX4(a[mf][0], a[mf][1], a[mf][2], a[mf][3],
                      Qs + (it * 32 + mf * 16 + lrow) * QSTR + coff);
#pragma unroll
            for (int bi = 0; bi < 4; bi++)
                LDMX4(bb[bi][0], bb[bi][1], bb[bi][2], bb[bi][3],
                      Ks + (bi * 16 + lrow) * QSTR + coff);
#pragma unroll
            for (int mf = 0; mf < 2; mf++)
#pragma unroll
                for (int bi = 0; bi < 4; bi++) {
                    uint32_t blo[2] = { bb[bi][0], bb[bi][2] };
                    uint32_t bhi[2] = { bb[bi][1], bb[bi][3] };
                    MMA16816(acc[mf][bi * 2 + 0], a[mf], blo);
                    MMA16816(acc[mf][bi * 2 + 1], a[mf], bhi);
                }
        }

        // row-wise LSE: each (mf, rl) row held by quad (lane&3)
#pragma unroll
        for (int mf = 0; mf < 2; mf++)
#pragma unroll
            for (int rl = 0; rl < 2; rl++) {
                float amax = -1e30f;
#pragma unroll
                for (int nf = 0; nf < 8; nf++) {
                    amax = fmaxf(amax, acc[mf][nf][rl * 2 + 0]);
                    amax = fmaxf(amax, acc[mf][nf][rl * 2 + 1]);
                }
                amax = fmaxf(amax, __shfl_xor_sync(0xffffffffu, amax, 1));
                amax = fmaxf(amax, __shfl_xor_sync(0xffffffffu, amax, 2));
                float se = 0.f;
#pragma unroll
                for (int nf = 0; nf < 8; nf++) {
                    se += __expf(GAMMA * (acc[mf][nf][rl * 2 + 0] - amax));
                    se += __expf(GAMMA * (acc[mf][nf][rl * 2 + 1] - amax));
                }
                se += __shfl_xor_sync(0xffffffffu, se, 1);
                se += __shfl_xor_sync(0xffffffffu, se, 2);
                if ((lane & 3) == 0) att += amax + __logf(se) * (1.f / GAMMA);
            }
    }

    float tot = block_reduce_256(att, red);
    if (tid == 0) out[b] -= tot;
}

// ---------------------------------------------------------------------------
extern "C" void kernel_launch(void* const* d_in, const int* in_sizes, int n_in,
                              void* d_out, int out_size) {
    (void)in_sizes; (void)n_in; (void)out_size;
    const float* x   = (const float*)d_in[0];
    const float* z   = (const float*)d_in[1];
    const float* We  = (const float*)d_in[2];
    const float* ebv = (const float*)d_in[3];
    const float* vb  = (const float*)d_in[4];
    const float* pos = (const float*)d_in[5];
    const float* Wm  = (const float*)d_in[6];
    const float* WQ  = (const float*)d_in[7];
    const float* WK  = (const float*)d_in[8];
    float* out = (float*)d_out;

    size_t shg = (size_t)3 * ATILE;      // 202752 B
    size_t sha = (size_t)2 * 64 * QSTR;  // 67584 B

    cudaFuncSetAttribute(kgemm,  cudaFuncAttributeMaxDynamicSharedMemorySize, (int)shg);
    cudaFuncSetAttribute(kalite, cudaFuncAttributeMaxDynamicSharedMemorySize, (int)sha);

    kprepB<<<dim3(14, 16), 256>>>(Wm, WQ, WK, We);
    kgemm<<<512, 256, shg>>>(x, z, ebv, pos, vb, out);
    kalite<<<1024, 256, sha>>>(out);
}

// round 17
// speedup vs baseline: 1.0600x; 1.0600x over previous
#include <cuda_runtime.h>
#include <cuda_bf16.h>
#include <stdint.h>
#include <math.h>

#define GAMMA 0.25f
#define RSTRIDE 528              // A smem row pitch (256 bf16 + 16B pad), 33%8=1 conflict-free
#define ABYTES  135168           // 256 * RSTRIDE
#define CSTRIDE 144              // B chunk row pitch (64 bf16 = 128B + 16 pad), 9%8=1
#define CBUF    18432            // 128 * CSTRIDE
#define QSTR    528

// ---------------------------------------------------------------------------
// device scratch (static — no cudaMalloc allowed)
// ---------------------------------------------------------------------------
__device__ __align__(16) __nv_bfloat16 g_Bg[14 * 128 * 256];    // 14 B tiles [n][k]
__device__ __align__(16) __nv_bfloat16 g_qbf[65536 * 256];      // Q scratch bf16
__device__ __align__(16) __nv_bfloat16 g_kbf[65536 * 256];      // K scratch bf16

__device__ __forceinline__ uint32_t smem_u32(const void* p) {
    uint32_t a;
    asm("{ .reg .u64 t; cvta.to.shared.u64 t, %1; cvt.u32.u64 %0, t; }" : "=r"(a) : "l"(p));
    return a;
}

#define LDMX4(r0, r1, r2, r3, addr) \
    asm volatile("ldmatrix.sync.aligned.m8n8.x4.shared.b16 {%0,%1,%2,%3}, [%4];" \
                 : "=r"(r0), "=r"(r1), "=r"(r2), "=r"(r3) : "r"(addr))

#define MMA16816(d, a, b) \
    asm volatile("mma.sync.aligned.m16n8k16.row.col.f32.bf16.bf16.f32 " \
                 "{%0,%1,%2,%3}, {%4,%5,%6,%7}, {%8,%9}, {%0,%1,%2,%3};" \
                 : "+f"((d)[0]), "+f"((d)[1]), "+f"((d)[2]), "+f"((d)[3]) \
                 : "r"((a)[0]), "r"((a)[1]), "r"((a)[2]), "r"((a)[3]), \
                   "r"((b)[0]), "r"((b)[1]))

#define CPA16(dst, src) \
    asm volatile("cp.async.cg.shared.global [%0], [%1], 16;" :: "r"(dst), "l"(src) : "memory")
#define CPA_COMMIT() asm volatile("cp.async.commit_group;" ::: "memory")

// ---------------------------------------------------------------------------
__device__ __forceinline__ float block_reduce_256(float v, float* red) {
#pragma unroll
    for (int o = 16; o > 0; o >>= 1) v += __shfl_xor_sync(0xffffffffu, v, o);
    int w = threadIdx.x >> 5;
    if ((threadIdx.x & 31) == 0) red[w] = v;
    __syncthreads();
    if (threadIdx.x < 8) {
        v = red[threadIdx.x];
#pragma unroll
        for (int o = 4; o > 0; o >>= 1) v += __shfl_xor_sync(0x000000ffu, v, o);
    }
    return v;
}

// ---------------------------------------------------------------------------
// kprepB: build 14 dense bf16 B tiles [n][k] — one uint4 store per thread
// ---------------------------------------------------------------------------
extern "C" __global__ void __launch_bounds__(256)
kprepB(const float* __restrict__ Wm, const float* __restrict__ WQ,
       const float* __restrict__ WK, const float* __restrict__ We) {
    int nt = blockIdx.x;
    __nv_bfloat16* img = g_Bg + (size_t)nt * 128 * 256;
    int f0 = (blockIdx.y * 256 + threadIdx.x) * 8;   // grid.y = 16
    int n = f0 >> 8, k0 = f0 & 255;
    __nv_bfloat16 tmp[8];
#pragma unroll
    for (int i = 0; i < 8; i++) {
        int k = k0 + i;
        float v;
        if (nt < 8)        v = Wm[k * 1024 + nt * 128 + n];
        else if (nt < 10)  v = WQ[((nt - 8) * 128 + n) * 256 + k];
        else if (nt < 12)  v = WK[((nt - 10) * 128 + n) * 256 + k];
        else {
            int ng = (nt - 12) * 128 + n;
            v = (ng < 192) ? We[k * 192 + ng] : 0.f;
        }
        tmp[i] = __float2bfloat16(v);
    }
    *(uint4*)(img + f0) = *(uint4*)tmp;
}

// ---------------------------------------------------------------------------
// kgemm: grid 256, 256 threads (8 warps). CTA tile 256(M) x 128(N):
//   warp grid 4(m) x 2(n), warp tile 64x64 -> 16 MAC per smem byte (vs 10.7),
//   lifting the smem-crossbar roofline above the tensor roofline.
//   A (4 batch elems, 132KB) resident; B streamed in 64-kcol chunks (18KB),
//   4-buffer cp.async ring, prefetch distance 3, one sync per chunk.
//   Fused: z->bf16 + quad_z/bias/pos, phi_mem relu^2, Q/K bf16 stores,
//   x-side consume on nt=12/13.
// ---------------------------------------------------------------------------
extern "C" __global__ void __launch_bounds__(256, 1)
kgemm(const float* __restrict__ x, const float* __restrict__ z,
      const float* __restrict__ eb, const float* __restrict__ pos,
      const float* __restrict__ vb, float* __restrict__ out) {
    extern __shared__ char smem[];
    __shared__ float zred[8][4], wred[8];
    uint32_t sb = smem_u32(smem);
    const uint32_t As = sb;
    const uint32_t Bbase = sb + ABYTES;
    int tid = threadIdx.x, lane = tid & 31, w = tid >> 5;
    int wm = w >> 1, wn = w & 1;          // 4(m) x 2(n) warp grid
    int mtile = blockIdx.x;

    // --- prologue: prefetch chunks t = 0,1,2 (nt=0, cn=0..2) ---
#pragma unroll
    for (int t = 0; t < 3; t++) {
        const char* src = (const char*)g_Bg + t * 128;   // nt=0, col-chunk t
        uint32_t dst = Bbase + (uint32_t)t * CBUF;
#pragma unroll
        for (int j = 0; j < 4; j++) {
            int u = tid + j * 256;                // 1024 16B units
            int n = u >> 3, kslot = u & 7;
            CPA16(dst + n * CSTRIDE + kslot * 16, src + n * 512 + kslot * 16);
        }
        CPA_COMMIT();
    }

    // --- A load: z f32 -> bf16 smem (256 rows) + fused z statistics ---
    const float* zb = z + (size_t)mtile * 256 * 256;
    float zacc[4] = {0.f, 0.f, 0.f, 0.f};
#pragma unroll
    for (int i = 0; i < 32; i++) {
        int f = tid + i * 256;               // chunk of 8 floats (8192 total)
        int row = f >> 5, c8 = (f & 31) * 8;
        const float4* zp = (const float4*)(zb + row * 256 + c8);
        float4 v0 = zp[0], v1 = zp[1];
        int prow = row & 63;
        float4 e0 = *(const float4*)(eb + c8);
        float4 e1 = *(const float4*)(eb + c8 + 4);
        float4 p0 = *(const float4*)(pos + prow * 256 + c8);
        float4 p1 = *(const float4*)(pos + prow * 256 + c8 + 4);
        float t =
            v0.x * (0.5f * v0.x - e0.x - p0.x) + v0.y * (0.5f * v0.y - e0.y - p0.y) +
            v0.z * (0.5f * v0.z - e0.z - p0.z) + v0.w * (0.5f * v0.w - e0.w - p0.w) +
            v1.x * (0.5f * v1.x - e1.x - p1.x) + v1.y * (0.5f * v1.y - e1.y - p1.y) +
            v1.z * (0.5f * v1.z - e1.z - p1.z) + v1.w * (0.5f * v1.w - e1.w - p1.w);
        zacc[i >> 3] += t;                   // rows i*8..i*8+7 all in elem i>>3
        uint4 pk;
        __nv_bfloat162 bt;
        bt = __floats2bfloat162_rn(v0.x, v0.y); pk.x = *(uint32_t*)&bt;
        bt = __floats2bfloat162_rn(v0.z, v0.w); pk.y = *(uint32_t*)&bt;
        bt = __floats2bfloat162_rn(v1.x, v1.y); pk.z = *(uint32_t*)&bt;
        bt = __floats2bfloat162_rn(v1.z, v1.w); pk.w = *(uint32_t*)&bt;
        *(uint4*)(smem + row * RSTRIDE + (f & 31) * 16) = pk;
    }

    float msum = 0.f;          // phi_mem   (this warp's batch elem = wm)
    float xsum = 0.f;          // x-side    (this warp's batch elem = wm)
    const float* xb = x + (size_t)mtile * 4 * 12288;
    int lrow = lane & 15, lhi = lane >> 4;

    for (int nt = 0; nt < 14; nt++) {
        float acc[4][8][4];
#pragma unroll
        for (int mi = 0; mi < 4; mi++)
#pragma unroll
            for (int nf = 0; nf < 8; nf++)
#pragma unroll
                for (int r = 0; r < 4; r++) acc[mi][nf][r] = 0.f;

        for (int cn = 0; cn < 4; cn++) {
            int t = nt * 4 + cn;
            asm volatile("cp.async.wait_group 2;" ::: "memory");
            __syncthreads();     // chunk t resident; also fences prev compute

            // prefetch chunk t+3 into buffer (t+3)&3 (holds chunk t-1: done)
            int tp = t + 3;
            if (tp < 56) {
                int pnt = tp >> 2, pcn = tp & 3;
                const char* src = (const char*)g_Bg + (size_t)pnt * 65536 + pcn * 128;
                uint32_t dst = Bbase + (uint32_t)(tp & 3) * CBUF;
#pragma unroll
                for (int j = 0; j < 4; j++) {
                    int u = tid + j * 256;
                    int n = u >> 3, kslot = u & 7;
                    CPA16(dst + n * CSTRIDE + kslot * 16, src + n * 512 + kslot * 16);
                }
            }
            CPA_COMMIT();        // empty group ok — keeps ring invariant

            uint32_t Bb = Bbase + (uint32_t)(t & 3) * CBUF;
#pragma unroll
            for (int kk = 0; kk < 4; kk++) {
                int ks = cn * 4 + kk;
                uint32_t af[4][4], bfr[4][4];
#pragma unroll
                for (int mi = 0; mi < 4; mi++)
                    LDMX4(af[mi][0], af[mi][1], af[mi][2], af[mi][3],
                          As + (wm * 64 + mi * 16 + lrow) * RSTRIDE + ks * 32 + lhi * 16);
#pragma unroll
                for (int bi = 0; bi < 4; bi++)
                    LDMX4(bfr[bi][0], bfr[bi][1], bfr[bi][2], bfr[bi][3],
                          Bb + (wn * 64 + bi * 16 + lrow) * CSTRIDE + kk * 32 + lhi * 16);
#pragma unroll
                for (int mi = 0; mi < 4; mi++)
#pragma unroll
                    for (int bi = 0; bi < 4; bi++) {
                        uint32_t blo[2] = { bfr[bi][0], bfr[bi][2] };
                        uint32_t bhi[2] = { bfr[bi][1], bfr[bi][3] };
                        MMA16816(acc[mi][bi * 2 + 0], af[mi], blo);
                        MMA16816(acc[mi][bi * 2 + 1], af[mi], bhi);
                    }
            }
        }

        // ---- epilogue for this N-tile (acc is register-local; no sync) ----
        if (nt < 8) {
            // phi_mem: relu^2 reduce in-register
#pragma unroll
            for (int mi = 0; mi < 4; mi++)
#pragma unroll
                for (int nf = 0; nf < 8; nf++)
#pragma unroll
                    for (int r = 0; r < 4; r++) {
                        float v = fmaxf(acc[mi][nf][r], 0.f);
                        msum += v * v;
                    }
        } else if (nt < 12) {
            __nv_bfloat16* gout = (nt < 10) ? g_qbf : g_kbf;
            int tc = (nt < 10) ? (nt - 8) : (nt - 10);
            int colbase = tc * 128 + wn * 64 + (lane & 3) * 2;
            int rowbase = mtile * 256 + wm * 64 + (lane >> 2);
#pragma unroll
            for (int mi = 0; mi < 4; mi++)
#pragma unroll
                for (int nf = 0; nf < 8; nf++) {
                    int col = colbase + nf * 8;
                    int r0 = rowbase + mi * 16;
                    __nv_bfloat162 lo = __floats2bfloat162_rn(acc[mi][nf][0], acc[mi][nf][1]);
                    __nv_bfloat162 hi = __floats2bfloat162_rn(acc[mi][nf][2], acc[mi][nf][3]);
                    *(uint32_t*)(gout + (size_t)r0 * 256 + col) = *(uint32_t*)&lo;
                    *(uint32_t*)(gout + (size_t)(r0 + 8) * 256 + col) = *(uint32_t*)&hi;
                }
        } else {
            // enc tiles: consume accumulators directly against x (coalesced).
            // k = (nt-12)*128 + wn*64 + nf*8 + (lane&3)*2 + r  (valid k<192)
            int tc = nt - 12;
            if (!(tc == 1 && wn == 1)) {           // those cols are k>=192 (pad)
                int c = tc * 2 + wn;               // channel = k>>6
#pragma unroll
                for (int mi = 0; mi < 4; mi++)
#pragma unroll
                    for (int rp = 0; rp < 2; rp++) {
                        int l = wm * 64 + mi * 16 + rp * 8 + (lane >> 2);  // local row
                        int p = l & 63;            // l>>6 == wm always
                        size_t vboff = (size_t)c * 4096 + (p >> 3) * 512 +
                                       (p & 7) * 8 + (lane & 3) * 2;
                        size_t base0 = (size_t)wm * 12288 + vboff;
#pragma unroll
                        for (int nf = 0; nf < 8; nf++) {
                            size_t off = base0 + nf * 64;  // ii = (p>>3)*8 + nf
                            float2 xv = *(const float2*)(xb + off);
                            float2 vv = *(const float2*)(vb + vboff + nf * 64);
                            float a0 = acc[mi][nf][rp * 2 + 0];
                            float a1 = acc[mi][nf][rp * 2 + 1];
                            xsum += xv.x * (0.5f * xv.x - vv.x - a0)
                                  + xv.y * (0.5f * xv.y - vv.y - a1);
                        }
                    }
            }
        }
    }

    // ---- final per-batch reductions: out[b] = zterms + xterms - phi_mem ----
    float wsum = xsum - msum;          // this warp's batch elem = wm
#pragma unroll
    for (int o = 16; o > 0; o >>= 1) {
        wsum += __shfl_xor_sync(0xffffffffu, wsum, o);
#pragma unroll
        for (int e = 0; e < 4; e++)
            zacc[e] += __shfl_xor_sync(0xffffffffu, zacc[e], o);
    }
    if (lane == 0) {
        wred[w] = wsum;
#pragma unroll
        for (int e = 0; e < 4; e++) zred[w][e] = zacc[e];
    }
    __syncthreads();
    if (tid == 0) {
#pragma unroll
        for (int e = 0; e < 4; e++) {
            float s = wred[2 * e] + wred[2 * e + 1];
#pragma unroll
            for (int ww = 0; ww < 8; ww++) s += zred[ww][e];
            out[4 * mtile + e] = s;
        }
    }
}

// ---------------------------------------------------------------------------
// kalite: out[b] -= phi_att. Logits via mma.sync from bf16 Q,K scratch.
//   Block = batch b; warp w = head w, two 32-row tasks sequentially
//   (halves acc registers -> 2 CTAs/SM). Overlaps kgemm tail waves.
// ---------------------------------------------------------------------------
extern "C" __global__ void __launch_bounds__(256, 2)
kalite(float* __restrict__ out) {
    extern __shared__ char sm[];
    __shared__ float red[8];
    uint32_t sb = smem_u32(sm);
    uint32_t Qs = sb, Ks = sb + 64 * QSTR;
    int b = blockIdx.x, tid = threadIdx.x, lane = tid & 31, w = tid >> 5;

    const uint4* qsrc = (const uint4*)(g_qbf + (size_t)b * 64 * 256);
    const uint4* ksrc = (const uint4*)(g_kbf + (size_t)b * 64 * 256);
#pragma unroll
    for (int i = 0; i < 8; i++) {
        int c = tid + i * 256;               // 2048 chunks each
        int row = c >> 5, cc = (c & 31) * 16;
        *(uint4*)(sm + row * QSTR + cc) = qsrc[c];
        *(uint4*)(sm + 64 * QSTR + row * QSTR + cc) = ksrc[c];
    }
    __syncthreads();

    int lrow = lane & 15, lhi = lane >> 4;
    float att = 0.f;

#pragma unroll
    for (int it = 0; it < 2; it++) {         // row-half of this head's 64 rows
        float acc[2][8][4];
#pragma unroll
        for (int mf = 0; mf < 2; mf++)
#pragma unroll
            for (int nf = 0; nf < 8; nf++)
#pragma unroll
                for (int r = 0; r < 4; r++) acc[mf][nf][r] = 0.f;

#pragma unroll
        for (int kc = 0; kc < 2; kc++) {
            uint32_t coff = w * 64 + kc * 32 + lhi * 16;
            uint32_t a[2][4], bb[4][4];
#pragma unroll
            for (int mf = 0; mf < 2; mf++)
                LDMX4(a[mf][0], a[mf][1], a[mf][2], a[mf][3],
                      Qs + (it * 32 + mf * 16 + lrow) * QSTR + coff);
#pragma unroll
            for (int bi = 0; bi < 4; bi++)
                LDMX4(bb[bi][0], bb[bi][1], bb[bi][2], bb[bi][3],
                      Ks + (bi * 16 + lrow) * QSTR + coff);
#pragma unroll
            for (int mf = 0; mf < 2; mf++)
#pragma unroll
                for (int bi = 0; bi < 4; bi++) {
                    uint32_t blo[2] = { bb[bi][0], bb[bi][2] };
                    uint32_t bhi[2] = { bb[bi][1], bb[bi][3] };
                    MMA16816(acc[mf][bi * 2 + 0], a[mf], blo);
                    MMA16816(acc[mf][bi * 2 + 1], a[mf], bhi);
                }
        }

        // row-wise LSE: each (mf, rl) row held by quad (lane&3)
#pragma unroll
        for (int mf = 0; mf < 2; mf++)
#pragma unroll
            for (int rl = 0; rl < 2; rl++) {
                float amax = -1e30f;
#pragma unroll
                for (int nf = 0; nf < 8; nf++) {
                    amax = fmaxf(amax, acc[mf][nf][rl * 2 + 0]);
                    amax = fmaxf(amax, acc[mf][nf][rl * 2 + 1]);
                }
                amax = fmaxf(amax, __shfl_xor_sync(0xffffffffu, amax, 1));
                amax = fmaxf(amax, __shfl_xor_sync(0xffffffffu, amax, 2));
                float se = 0.f;
#pragma unroll
                for (int nf = 0; nf < 8; nf++) {
                    se += __expf(GAMMA * (acc[mf][nf][rl * 2 + 0] - amax));
                    se += __expf(GAMMA * (acc[mf][nf][rl * 2 + 1] - amax));
                }
                se += __shfl_xor_sync(0xffffffffu, se, 1);
                se += __shfl_xor_sync(0xffffffffu, se, 2);
                if ((lane & 3) == 0) att += amax + __logf(se) * (1.f / GAMMA);
            }
    }

    float tot = block_reduce_256(att, red);
    if (tid == 0) out[b] -= tot;
}

// ---------------------------------------------------------------------------
extern "C" void kernel_launch(void* const* d_in, const int* in_sizes, int n_in,
                              void* d_out, int out_size) {
    (void)in_sizes; (void)n_in; (void)out_size;
    const float* x   = (const float*)d_in[0];
    const float* z   = (const float*)d_in[1];
    const float* We  = (const float*)d_in[2];
    const float* ebv = (const float*)d_in[3];
    const float* vb  = (const float*)d_in[4];
    const float* pos = (const float*)d_in[5];
    const float* Wm  = (const float*)d_in[6];
    const float* WQ  = (const float*)d_in[7];
    const float* WK  = (const float*)d_in[8];
    float* out = (float*)d_out;

    size_t shg = (size_t)ABYTES + 4 * CBUF;   // 135168 + 73728 = 208896 B
    size_t sha = (size_t)2 * 64 * QSTR;       // 67584 B

    cudaFuncSetAttribute(kgemm,  cudaFuncAttributeMaxDynamicSharedMemorySize, (int)shg);
    cudaFuncSetAttribute(kalite, cudaFuncAttributeMaxDynamicSharedMemorySize, (int)sha);

    kprepB<<<dim3(14, 16), 256>>>(Wm, WQ, WK, We);
    kgemm<<<256, 256, shg>>>(x, z, ebv, pos, vb, out);
    kalite<<<1024, 256, sha>>>(out);
}